// round 12
// baseline (speedup 1.0000x reference)
#include <cuda_runtime.h>
#include <cuda_fp16.h>
#include <math.h>
#include <stdint.h>

// Problem constants (fixed for MixtureOfExperts_498216206779)
#define NB 4
#define NT 2048
#define ND 1024
#define NH 4096
#define NE 8
#define NTOK (NB*NT)          // 8192
#define CAP 1024
#define MT (NE*CAP)           // 8192

// ---------------- scratch (device globals; no allocation allowed) ----------
__device__ float g_probs[NTOK*NE];
__device__ float g_lse2[NTOK];
__device__ int   g_expidx[NTOK];
__device__ float g_expprob[NTOK];
__device__ int   g_sorted_tok[NTOK];
__device__ int   g_counts[NE];
__device__ int   g_tok_of_slot[MT];
__device__ float g_scale[NTOK];
// fp16 buffers (single precision pass; error budget ~4.2e-4 < 1e-3)
__device__ __half g_xt[(size_t)NTOK*ND];    // tokens, TOKEN order [N][K]
__device__ __half g_hh[(size_t)MT*NH];      // hidden, slot order [M][K]
__device__ __half g_w1h[(size_t)NE*ND*NH];  // [E][N=NH][K=ND]
__device__ __half g_w2h[(size_t)NE*NH*ND];  // [E][N=ND][K=NH]

__device__ __forceinline__ uint32_t smem_u32(const void* p) {
    return (uint32_t)__cvta_generic_to_shared((void*)p);
}

// ------------- weight transpose + fp16 convert: [E][K][N] -> [E][N][K] -----
template<int K, int N>
__global__ void wconv_kernel(const float* __restrict__ W,
                             __half* __restrict__ Wh)
{
    __shared__ float tile[64][33];
    int e = blockIdx.z;
    int n0 = blockIdx.x * 32, k0 = blockIdx.y * 64;
    const float* We = W + (size_t)e * K * N;
    int tx = threadIdx.x, ty = threadIdx.y;   // (32, 8)
    #pragma unroll
    for (int i = 0; i < 8; i++) {
        int k = k0 + ty + i*8;
        tile[ty + i*8][tx] = We[(size_t)k * N + n0 + tx];
    }
    __syncthreads();
    __half* Whe = Wh + (size_t)e * K * N;
    #pragma unroll
    for (int i = 0; i < 4; i++) {
        int n = n0 + ty + i*8;
        float a = tile[2*tx][ty + i*8];
        float b = tile[2*tx+1][ty + i*8];
        *(__half2*)(Whe + (size_t)n * K + k0 + 2*tx) = __floats2half2_rn(a, b);
    }
}

// ---------------- router: logits/softmax/argmax/lse^2 + fp16 token copy ----
__global__ void router_kernel(const float* __restrict__ x,
                              const float* __restrict__ Wg)
{
    int warp = (blockIdx.x * blockDim.x + threadIdx.x) >> 5;
    int lane = threadIdx.x & 31;
    if (warp >= NTOK) return;
    const float* xr = x + (size_t)warp * ND;
    float acc[NE] = {0,0,0,0,0,0,0,0};
    for (int d = lane; d < ND; d += 32) {
        float xv = xr[d];
        const float* wr = Wg + d * NE;
        #pragma unroll
        for (int e = 0; e < NE; e++) acc[e] += xv * wr[e];
    }
    // fp16 token-order copy (row is hot in L1/L2)
    __half* xo = g_xt + (size_t)warp * ND;
    for (int d2 = lane; d2 < ND/2; d2 += 32) {
        float2 v = ((const float2*)xr)[d2];
        ((__half2*)xo)[d2] = __floats2half2_rn(v.x, v.y);
    }
    #pragma unroll
    for (int e = 0; e < NE; e++) {
        #pragma unroll
        for (int o = 16; o > 0; o >>= 1)
            acc[e] += __shfl_xor_sync(0xFFFFFFFFu, acc[e], o);
    }
    if (lane == 0) {
        float m = acc[0]; int am = 0;
        #pragma unroll
        for (int e = 1; e < NE; e++) if (acc[e] > m) { m = acc[e]; am = e; }
        float pe[NE]; float s = 0.f;
        #pragma unroll
        for (int e = 0; e < NE; e++) { pe[e] = expf(acc[e] - m); s += pe[e]; }
        float inv = 1.0f / s;
        #pragma unroll
        for (int e = 0; e < NE; e++) g_probs[warp*NE + e] = pe[e] * inv;
        float lse = logf(s) + m;
        g_lse2[warp]    = lse * lse;
        g_expidx[warp]  = am;
        g_expprob[warp] = pe[am] * inv;
    }
}

// ------------- stable ranks via warp-shuffle scan (1 block, 1024 thr) ------
__global__ void rank_kernel(float* __restrict__ out)
{
    __shared__ unsigned long long wtot0[32], wtot1[32];
    __shared__ unsigned long long woff0[32], woff1[32];
    __shared__ int sstart[NE];
    int t = threadIdx.x;
    int lane = t & 31, w = t >> 5;
    int base = t * 8;
    int e_arr[8];
    int cnt[NE] = {0,0,0,0,0,0,0,0};
    #pragma unroll
    for (int i = 0; i < 8; i++) { int e = g_expidx[base+i]; e_arr[i] = e; cnt[e]++; }
    unsigned long long p0 = 0, p1 = 0;
    #pragma unroll
    for (int e = 0; e < 4; e++) {
        p0 |= (unsigned long long)cnt[e]   << (16*e);
        p1 |= (unsigned long long)cnt[e+4] << (16*e);
    }
    // warp inclusive scan (packed 4x16-bit lanes per u64; warp total <= 256)
    unsigned long long s0 = p0, s1 = p1;
    #pragma unroll
    for (int o = 1; o < 32; o <<= 1) {
        unsigned long long v0 = __shfl_up_sync(0xFFFFFFFFu, s0, o);
        unsigned long long v1 = __shfl_up_sync(0xFFFFFFFFu, s1, o);
        if (lane >= o) { s0 += v0; s1 += v1; }
    }
    if (lane == 31) { wtot0[w] = s0; wtot1[w] = s1; }
    for (int i = t; i < MT; i += 1024) g_tok_of_slot[i] = -1;
    __syncthreads();
    if (w == 0) {
        unsigned long long a0 = wtot0[lane], a1 = wtot1[lane];
        unsigned long long i0 = a0, i1 = a1;
        #pragma unroll
        for (int o = 1; o < 32; o <<= 1) {
            unsigned long long v0 = __shfl_up_sync(0xFFFFFFFFu, i0, o);
            unsigned long long v1 = __shfl_up_sync(0xFFFFFFFFu, i1, o);
            if (lane >= o) { i0 += v0; i1 += v1; }
        }
        woff0[lane] = i0 - a0;  // exclusive warp offset
        woff1[lane] = i1 - a1;
        if (lane == 31) {
            int s = 0;
            #pragma unroll
            for (int e = 0; e < NE; e++) {
                int tot = (e < 4) ? (int)((i0 >> (16*e)) & 0xFFFF)
                                  : (int)((i1 >> (16*(e-4))) & 0xFFFF);
                sstart[e] = s; s += tot; g_counts[e] = tot;
            }
        }
    }
    __syncthreads();
    unsigned long long ex0 = woff0[w] + (s0 - p0);
    unsigned long long ex1 = woff1[w] + (s1 - p1);
    int loc[NE];
    #pragma unroll
    for (int e = 0; e < 4; e++) {
        loc[e]   = (int)((ex0 >> (16*e)) & 0xFFFF);
        loc[e+4] = (int)((ex1 >> (16*e)) & 0xFFFF);
    }
    #pragma unroll
    for (int i = 0; i < 8; i++) {
        int n = base + i, e = e_arr[i];
        int r = loc[e]++;
        g_sorted_tok[sstart[e] + r] = n;
        if (r < CAP) {
            g_tok_of_slot[e*CAP + r] = n;
        } else {
            // dropped token: its output row is exactly zero
            float4 z = make_float4(0.f, 0.f, 0.f, 0.f);
            float4* orow = (float4*)(out + (size_t)n * ND);
            for (int q = 0; q < ND/4; q++) orow[q] = z;
        }
    }
    __syncthreads();
    #pragma unroll
    for (int i = 0; i < 8; i++) {
        int n = base + i;
        g_scale[n] = g_expprob[g_sorted_tok[n]];
    }
}

// ================== mma.sync fp16 single-pass grouped GEMM =================
// 128x128 block, 4 warps, 64x64 warp tile, 4-stage cp.async pipeline.
// PHASE1 gathers A rows from token-order g_xt via g_tok_of_slot (zfill -1).
__device__ __forceinline__ float gelu_exact(float v) {
    return 0.5f * v * (1.0f + erff(v * 0.70710678118654752f));
}

#define CP_ASYNC16(dst, src) \
    asm volatile("cp.async.cg.shared.global [%0], [%1], 16;" :: "r"(dst), "l"(src))
#define CP_ASYNC16Z(dst, src, ssz) \
    asm volatile("cp.async.cg.shared.global [%0], [%1], 16, %2;" :: "r"(dst), "l"(src), "r"(ssz))
#define CP_COMMIT() asm volatile("cp.async.commit_group;" ::: "memory")
#define CP_WAITG(n) asm volatile("cp.async.wait_group %0;" :: "n"(n) : "memory")

__device__ __forceinline__ void ldsm4(uint32_t* r, uint32_t addr) {
    asm volatile("ldmatrix.sync.aligned.m8n8.x4.shared.b16 {%0,%1,%2,%3}, [%4];"
                 : "=r"(r[0]), "=r"(r[1]), "=r"(r[2]), "=r"(r[3]) : "r"(addr));
}
__device__ __forceinline__ void mma16816(float* d, const uint32_t* a, const uint32_t* b) {
    asm volatile(
        "mma.sync.aligned.m16n8k16.row.col.f32.f16.f16.f32 "
        "{%0,%1,%2,%3}, {%4,%5,%6,%7}, {%8,%9}, {%0,%1,%2,%3};"
        : "+f"(d[0]), "+f"(d[1]), "+f"(d[2]), "+f"(d[3])
        : "r"(a[0]), "r"(a[1]), "r"(a[2]), "r"(a[3]), "r"(b[0]), "r"(b[1]));
}

// SMEM: 4 stages x 2 matrices (A, B), each 128 rows x 80B pitch
#define PITCH 80
#define MATB  (128 * PITCH)        // 10240
#define STAGEB (2 * MATB)          // 20480
#define GSMEM (4 * STAGEB)         // 81920

template<int KTOT, int NTOT, bool PHASE2>
__global__ __launch_bounds__(128, 2)
void tgemm_kernel(const __half* __restrict__ A_g,
                  const __half* __restrict__ B_g,
                  const float* __restrict__ bias,
                  float* __restrict__ outp)
{
    extern __shared__ char smem[];
    uint32_t sbase = smem_u32(smem);
    int tid = threadIdx.x;
    int wid = tid >> 5, lane = tid & 31;
    int wm = wid & 1, wn = wid >> 1;          // warp grid 2(M) x 2(N), 64x64 tiles
    int bn = blockIdx.x, bm = blockIdx.y;
    int e = bm >> 3;                          // 8 M-blocks per expert

    const __half* Be = B_g + (size_t)e * NTOT * KTOT + (size_t)bn * 128 * KTOT;

    int r0 = tid >> 2, c0 = tid & 3;          // rows 0..31 base, 16B chunks

    // Per-thread A row pointers (PHASE1: gathered via slot->token map)
    const __half* arow[4];
    uint32_t asz[4];
    #pragma unroll
    for (int i = 0; i < 4; i++) {
        int row = r0 + i*32;
        if (!PHASE2) {
            int tok = g_tok_of_slot[bm*128 + row];
            arow[i] = A_g + (size_t)(tok < 0 ? 0 : tok) * KTOT;
            asz[i] = (tok < 0) ? 0u : 16u;
        } else {
            arow[i] = A_g + (size_t)(bm*128 + row) * KTOT;
            asz[i] = 16u;
        }
    }

    float acc[4][8][4];
    #pragma unroll
    for (int i = 0; i < 4; i++)
        #pragma unroll
        for (int j = 0; j < 8; j++)
            #pragma unroll
            for (int c = 0; c < 4; c++) acc[i][j][c] = 0.f;

    const int S = KTOT / 32;

    auto load_stage = [&](int s, int buf) {
        int k0 = s * 32;
        uint32_t sb = sbase + buf * STAGEB;
        const __half* gB = Be + (size_t)r0 * KTOT + k0 + c0 * 8;
        uint32_t so = r0 * PITCH + c0 * 16;
        #pragma unroll
        for (int i = 0; i < 4; i++) {
            uint32_t sstep = (i * 32) * PITCH;
            CP_ASYNC16Z(sb + so + sstep, arow[i] + k0 + c0 * 8, asz[i]);
            CP_ASYNC16(sb + MATB + so + sstep, gB + (size_t)(i * 32) * KTOT);
        }
        CP_COMMIT();
    };

    // ldmatrix lane decomposition
    int lr = lane & 7, lq = (lane >> 3) & 1, lh = lane >> 4;

    load_stage(0, 0);
    load_stage(1, 1);
    load_stage(2, 2);
    for (int s = 0; s < S; s++) {
        int buf = s & 3;
        if (s + 3 < S) {
            load_stage(s + 3, (s + 3) & 3);
            CP_WAITG(3);
        } else {
            int rem = S - 1 - s;
            if (rem == 2)      CP_WAITG(2);
            else if (rem == 1) CP_WAITG(1);
            else               CP_WAITG(0);
        }
        __syncthreads();

        uint32_t sb = sbase + buf * STAGEB;
        #pragma unroll
        for (int kk = 0; kk < 2; kk++) {
            uint32_t ah[4][4], bh[8][2];
            #pragma unroll
            for (int mi2 = 0; mi2 < 2; mi2++) {
                int row = wm*64 + mi2*32 + lr + lq*8;
                uint32_t off = row * PITCH + kk*32 + lh*16;
                ldsm4(ah[2*mi2], sb + off);
                int row2 = row + 16;
                uint32_t off2 = row2 * PITCH + kk*32 + lh*16;
                ldsm4(ah[2*mi2+1], sb + off2);
            }
            #pragma unroll
            for (int nj2 = 0; nj2 < 4; nj2++) {
                int row = wn*64 + nj2*16 + lr + lh*8;
                uint32_t off = row * PITCH + kk*32 + lq*16;
                uint32_t t[4];
                ldsm4(t, sb + MATB + off);
                bh[2*nj2][0] = t[0]; bh[2*nj2][1] = t[1];
                bh[2*nj2+1][0] = t[2]; bh[2*nj2+1][1] = t[3];
            }
            #pragma unroll
            for (int mi = 0; mi < 4; mi++)
                #pragma unroll
                for (int nj = 0; nj < 8; nj++)
                    mma16816(acc[mi][nj], ah[mi], bh[nj]);
        }
        __syncthreads();
    }

    // ---------------- epilogue --------------------------------------------
    int qr = lane >> 2, qc = lane & 3;
    float2 bv[8];
    #pragma unroll
    for (int nj = 0; nj < 8; nj++) {
        int colg = bn*128 + wn*64 + nj*8 + 2*qc;
        bv[nj] = *(const float2*)(bias + (size_t)e * NTOT + colg);
    }
    if (!PHASE2) {
        #pragma unroll
        for (int mi = 0; mi < 4; mi++)
            #pragma unroll
            for (int h = 0; h < 2; h++) {
                int rowg = bm*128 + wm*64 + mi*16 + qr + h*8;
                #pragma unroll
                for (int nj = 0; nj < 8; nj++) {
                    int colg = bn*128 + wn*64 + nj*8 + 2*qc;
                    float v0 = acc[mi][nj][2*h]   + bv[nj].x;
                    float v1 = acc[mi][nj][2*h+1] + bv[nj].y;
                    __half2 hv = __floats2half2_rn(gelu_exact(v0), gelu_exact(v1));
                    *(__half2*)(g_hh + (size_t)rowg * NTOT + colg) = hv;
                }
            }
    } else {
        #pragma unroll
        for (int mi = 0; mi < 4; mi++)
            #pragma unroll
            for (int h = 0; h < 2; h++) {
                int slot = bm*128 + wm*64 + mi*16 + qr + h*8;
                int tok = g_tok_of_slot[slot];
                if (tok >= 0) {
                    float sc = g_scale[tok];
                    float* orow = outp + (size_t)tok * NTOT;
                    #pragma unroll
                    for (int nj = 0; nj < 8; nj++) {
                        int colg = bn*128 + wn*64 + nj*8 + 2*qc;
                        float2 ov;
                        ov.x = (acc[mi][nj][2*h]   + bv[nj].x) * sc;
                        ov.y = (acc[mi][nj][2*h+1] + bv[nj].y) * sc;
                        *(float2*)(orow + colg) = ov;
                    }
                }
            }
    }
}

// ---------------- aux loss (deterministic reduction, 1 block) ---------------
__global__ void aux_kernel(float* __restrict__ out_aux)
{
    __shared__ float sh[1024];
    int t = threadIdx.x;
    float ls = 0.f;
    for (int n = t; n < NTOK; n += 1024) ls += g_lse2[n];
    float ps[NE] = {0,0,0,0,0,0,0,0};
    for (int n = t; n < NTOK; n += 1024) {
        #pragma unroll
        for (int e = 0; e < NE; e++) ps[e] += g_probs[n*NE + e];
    }
    __shared__ float red[NE + 1];
    sh[t] = ls; __syncthreads();
    for (int o = 512; o > 0; o >>= 1) { if (t < o) sh[t] += sh[t + o]; __syncthreads(); }
    if (t == 0) red[NE] = sh[0];
    __syncthreads();
    for (int e = 0; e < NE; e++) {
        sh[t] = ps[e]; __syncthreads();
        for (int o = 512; o > 0; o >>= 1) { if (t < o) sh[t] += sh[t + o]; __syncthreads(); }
        if (t == 0) red[e] = sh[0];
        __syncthreads();
    }
    if (t == 0) {
        float invN = 1.0f / (float)NTOK;
        float fb = 0.f;
        for (int e = 0; e < NE; e++) {
            float f_i = (float)g_counts[e] * invN;
            float p_i = red[e] * invN;
            fb += f_i * p_i;
        }
        float z = red[NE] * invN;
        out_aux[0] = 0.01f * (float)NE * fb + 0.001f * z;
    }
}

// ---------------------------------------------------------------------------
extern "C" void kernel_launch(void* const* d_in, const int* in_sizes, int n_in,
                              void* d_out, int out_size)
{
    const float* x  = (const float*)d_in[0];
    const float* Wg = (const float*)d_in[1];
    const float* W1 = (const float*)d_in[2];
    const float* b1 = (const float*)d_in[3];
    const float* W2 = (const float*)d_in[4];
    const float* b2 = (const float*)d_in[5];
    float* out = (float*)d_out;

    cudaFuncSetAttribute(tgemm_kernel<ND, NH, false>,
                         cudaFuncAttributeMaxDynamicSharedMemorySize, GSMEM);
    cudaFuncSetAttribute(tgemm_kernel<NH, ND, true>,
                         cudaFuncAttributeMaxDynamicSharedMemorySize, GSMEM);

    __half *xt, *hh, *w1h, *w2h;
    cudaGetSymbolAddress((void**)&xt,  g_xt);
    cudaGetSymbolAddress((void**)&hh,  g_hh);
    cudaGetSymbolAddress((void**)&w1h, g_w1h);
    cudaGetSymbolAddress((void**)&w2h, g_w2h);

    // weight transpose + fp16 convert (independent of routing)
    wconv_kernel<ND, NH><<<dim3(NH/32, ND/64, NE), dim3(32, 8)>>>(W1, w1h);
    wconv_kernel<NH, ND><<<dim3(ND/32, NH/64, NE), dim3(32, 8)>>>(W2, w2h);

    // routing chain (router also emits fp16 token-order copy)
    router_kernel<<<NTOK/8, 256>>>(x, Wg);
    rank_kernel<<<1, 1024>>>(out);

    // GEMM1: gathered A from g_xt -> gelu -> hidden (fp16, slot order)
    tgemm_kernel<ND, NH, false><<<dim3(NH/128, MT/128), 128, GSMEM>>>(
        xt, w1h, b1, out);
    // GEMM2: [MT,NH] @ W2t -> bias + scale -> scatter to out
    tgemm_kernel<NH, ND, true><<<dim3(ND/128, MT/128), 128, GSMEM>>>(
        hh, w2h, b2, out);

    if (out_size > NTOK * ND) {
        aux_kernel<<<1, 1024>>>(out + (size_t)NTOK * ND);
    }
}

// round 14
// speedup vs baseline: 1.0211x; 1.0211x over previous
#include <cuda_runtime.h>
#include <cuda_fp16.h>
#include <math.h>
#include <stdint.h>

// Problem constants (fixed for MixtureOfExperts_498216206779)
#define NB 4
#define NT 2048
#define ND 1024
#define NH 4096
#define NE 8
#define NTOK (NB*NT)          // 8192
#define CAP 1024
#define MT (NE*CAP)           // 8192

// ---------------- scratch (device globals; no allocation allowed) ----------
__device__ float g_probs[NTOK*NE];
__device__ float g_lse2[NTOK];
__device__ int   g_expidx[NTOK];
__device__ float g_expprob[NTOK];
__device__ int   g_rank[NTOK];
__device__ int   g_sorted_tok[NTOK];
__device__ int   g_counts[NE];
__device__ int   g_tok_of_slot[MT];
__device__ float g_scale[NTOK];
// fp16 buffers (single precision pass; error budget ~4.2e-4 < 1e-3)
__device__ __half g_xh[(size_t)MT*ND];      // tokens, slot order [M][K]
__device__ __half g_hh[(size_t)MT*NH];      // hidden, slot order [M][K]
__device__ __half g_w1h[(size_t)NE*ND*NH];  // [E][N=NH][K=ND]
__device__ __half g_w2h[(size_t)NE*NH*ND];  // [E][N=ND][K=NH]

__device__ __forceinline__ uint32_t smem_u32(const void* p) {
    return (uint32_t)__cvta_generic_to_shared((void*)p);
}

// ------------- weight transpose + fp16 convert: [E][K][N] -> [E][N][K] -----
template<int K, int N>
__global__ void wconv_kernel(const float* __restrict__ W,
                             __half* __restrict__ Wh)
{
    __shared__ float tile[64][33];
    int e = blockIdx.z;
    int n0 = blockIdx.x * 32, k0 = blockIdx.y * 64;
    const float* We = W + (size_t)e * K * N;
    int tx = threadIdx.x, ty = threadIdx.y;   // (32, 8)
    #pragma unroll
    for (int i = 0; i < 8; i++) {
        int k = k0 + ty + i*8;
        tile[ty + i*8][tx] = We[(size_t)k * N + n0 + tx];
    }
    __syncthreads();
    __half* Whe = Wh + (size_t)e * K * N;
    #pragma unroll
    for (int i = 0; i < 4; i++) {
        int n = n0 + ty + i*8;
        float a = tile[2*tx][ty + i*8];
        float b = tile[2*tx+1][ty + i*8];
        *(__half2*)(Whe + (size_t)n * K + k0 + 2*tx) = __floats2half2_rn(a, b);
    }
}

// ---------------- router: logits, softmax, argmax, lse^2 -------------------
__global__ void router_kernel(const float* __restrict__ x,
                              const float* __restrict__ Wg)
{
    int warp = (blockIdx.x * blockDim.x + threadIdx.x) >> 5;
    int lane = threadIdx.x & 31;
    if (warp >= NTOK) return;
    const float* xr = x + (size_t)warp * ND;
    float acc[NE] = {0,0,0,0,0,0,0,0};
    for (int d = lane; d < ND; d += 32) {
        float xv = xr[d];
        const float* wr = Wg + d * NE;
        #pragma unroll
        for (int e = 0; e < NE; e++) acc[e] += xv * wr[e];
    }
    #pragma unroll
    for (int e = 0; e < NE; e++) {
        #pragma unroll
        for (int o = 16; o > 0; o >>= 1)
            acc[e] += __shfl_xor_sync(0xFFFFFFFFu, acc[e], o);
    }
    if (lane == 0) {
        float m = acc[0]; int am = 0;
        #pragma unroll
        for (int e = 1; e < NE; e++) if (acc[e] > m) { m = acc[e]; am = e; }
        float pe[NE]; float s = 0.f;
        #pragma unroll
        for (int e = 0; e < NE; e++) { pe[e] = expf(acc[e] - m); s += pe[e]; }
        float inv = 1.0f / s;
        #pragma unroll
        for (int e = 0; e < NE; e++) g_probs[warp*NE + e] = pe[e] * inv;
        float lse = logf(s) + m;
        g_lse2[warp]    = lse * lse;
        g_expidx[warp]  = am;
        g_expprob[warp] = pe[am] * inv;
    }
}

// ------------- stable ranks via warp-shuffle scan (1 block, 1024 thr) ------
__global__ void rank_kernel()
{
    __shared__ unsigned long long wtot0[32], wtot1[32];
    __shared__ unsigned long long woff0[32], woff1[32];
    __shared__ int sstart[NE];
    int t = threadIdx.x;
    int lane = t & 31, w = t >> 5;
    int base = t * 8;
    int e_arr[8];
    int cnt[NE] = {0,0,0,0,0,0,0,0};
    #pragma unroll
    for (int i = 0; i < 8; i++) { int e = g_expidx[base+i]; e_arr[i] = e; cnt[e]++; }
    unsigned long long p0 = 0, p1 = 0;
    #pragma unroll
    for (int e = 0; e < 4; e++) {
        p0 |= (unsigned long long)cnt[e]   << (16*e);
        p1 |= (unsigned long long)cnt[e+4] << (16*e);
    }
    // warp inclusive scan (packed 4x16-bit lanes per u64; warp total <= 256)
    unsigned long long s0 = p0, s1 = p1;
    #pragma unroll
    for (int o = 1; o < 32; o <<= 1) {
        unsigned long long v0 = __shfl_up_sync(0xFFFFFFFFu, s0, o);
        unsigned long long v1 = __shfl_up_sync(0xFFFFFFFFu, s1, o);
        if (lane >= o) { s0 += v0; s1 += v1; }
    }
    if (lane == 31) { wtot0[w] = s0; wtot1[w] = s1; }
    for (int i = t; i < MT; i += 1024) g_tok_of_slot[i] = -1;
    __syncthreads();
    if (w == 0) {
        unsigned long long a0 = wtot0[lane], a1 = wtot1[lane];
        unsigned long long i0 = a0, i1 = a1;
        #pragma unroll
        for (int o = 1; o < 32; o <<= 1) {
            unsigned long long v0 = __shfl_up_sync(0xFFFFFFFFu, i0, o);
            unsigned long long v1 = __shfl_up_sync(0xFFFFFFFFu, i1, o);
            if (lane >= o) { i0 += v0; i1 += v1; }
        }
        woff0[lane] = i0 - a0;  // exclusive warp offset
        woff1[lane] = i1 - a1;
        if (lane == 31) {
            int s = 0;
            #pragma unroll
            for (int e = 0; e < NE; e++) {
                int tot = (e < 4) ? (int)((i0 >> (16*e)) & 0xFFFF)
                                  : (int)((i1 >> (16*(e-4))) & 0xFFFF);
                sstart[e] = s; s += tot; g_counts[e] = tot;
            }
        }
    }
    __syncthreads();
    unsigned long long ex0 = woff0[w] + (s0 - p0);
    unsigned long long ex1 = woff1[w] + (s1 - p1);
    int loc[NE];
    #pragma unroll
    for (int e = 0; e < 4; e++) {
        loc[e]   = (int)((ex0 >> (16*e)) & 0xFFFF);
        loc[e+4] = (int)((ex1 >> (16*e)) & 0xFFFF);
    }
    #pragma unroll
    for (int i = 0; i < 8; i++) {
        int n = base + i, e = e_arr[i];
        int r = loc[e]++;
        g_rank[n] = r;
        g_sorted_tok[sstart[e] + r] = n;
        if (r < CAP) g_tok_of_slot[e*CAP + r] = n;
    }
}

// ------------- gather tokens -> fp16 expert buffers ------------------------
__global__ void gather_kernel(const float* __restrict__ x, float* __restrict__ out)
{
    int n = blockIdx.x;
    int t = threadIdx.x;   // 256
    int e = g_expidx[n];
    int r = g_rank[n];
    if (t == 0) g_scale[n] = g_expprob[g_sorted_tok[n]];
    if (r < CAP) {
        size_t base = ((size_t)(e*CAP + r)) * ND + t*4;
        float4 v = ((const float4*)(x + (size_t)n * ND))[t];
        __half2 a = __floats2half2_rn(v.x, v.y);
        __half2 b = __floats2half2_rn(v.z, v.w);
        uint2 pk;
        pk.x = *(uint32_t*)&a;
        pk.y = *(uint32_t*)&b;
        *(uint2*)(g_xh + base) = pk;
    } else {
        float4 z = make_float4(0.f, 0.f, 0.f, 0.f);
        ((float4*)(out + (size_t)n * ND))[t] = z;
    }
}

// ================== mma.sync fp16 single-pass grouped GEMM =================
// 128x128 block, 4 warps, 64x64 warp tile, 4-stage cp.async pipeline.
__device__ __forceinline__ float gelu_exact(float v) {
    return 0.5f * v * (1.0f + erff(v * 0.70710678118654752f));
}

#define CP_ASYNC16(dst, src) \
    asm volatile("cp.async.cg.shared.global [%0], [%1], 16;" :: "r"(dst), "l"(src))
#define CP_COMMIT() asm volatile("cp.async.commit_group;" ::: "memory")
#define CP_WAITG(n) asm volatile("cp.async.wait_group %0;" :: "n"(n) : "memory")

__device__ __forceinline__ void ldsm4(uint32_t* r, uint32_t addr) {
    asm volatile("ldmatrix.sync.aligned.m8n8.x4.shared.b16 {%0,%1,%2,%3}, [%4];"
                 : "=r"(r[0]), "=r"(r[1]), "=r"(r[2]), "=r"(r[3]) : "r"(addr));
}
__device__ __forceinline__ void mma16816(float* d, const uint32_t* a, const uint32_t* b) {
    asm volatile(
        "mma.sync.aligned.m16n8k16.row.col.f32.f16.f16.f32 "
        "{%0,%1,%2,%3}, {%4,%5,%6,%7}, {%8,%9}, {%0,%1,%2,%3};"
        : "+f"(d[0]), "+f"(d[1]), "+f"(d[2]), "+f"(d[3])
        : "r"(a[0]), "r"(a[1]), "r"(a[2]), "r"(a[3]), "r"(b[0]), "r"(b[1]));
}

// SMEM: 4 stages x 2 matrices (A, B), each 128 rows x 80B pitch
#define PITCH 80
#define MATB  (128 * PITCH)        // 10240
#define STAGEB (2 * MATB)          // 20480
#define GSMEM (4 * STAGEB)         // 81920

template<int KTOT, int NTOT, bool PHASE2>
__global__ __launch_bounds__(128, 2)
void tgemm_kernel(const __half* __restrict__ A_g,
                  const __half* __restrict__ B_g,
                  const float* __restrict__ bias,
                  float* __restrict__ outp)
{
    extern __shared__ char smem[];
    uint32_t sbase = smem_u32(smem);
    int tid = threadIdx.x;
    int wid = tid >> 5, lane = tid & 31;
    int wm = wid & 1, wn = wid >> 1;          // warp grid 2(M) x 2(N), 64x64 tiles
    int bn = blockIdx.x, bm = blockIdx.y;
    int e = bm >> 3;                          // 8 M-blocks per expert

    const __half* Ae = A_g + (size_t)bm * 128 * KTOT;
    const __half* Be = B_g + (size_t)e * NTOT * KTOT + (size_t)bn * 128 * KTOT;

    float acc[4][8][4];
    #pragma unroll
    for (int i = 0; i < 4; i++)
        #pragma unroll
        for (int j = 0; j < 8; j++)
            #pragma unroll
            for (int c = 0; c < 4; c++) acc[i][j][c] = 0.f;

    const int S = KTOT / 32;

    int r0 = tid >> 2, c0 = tid & 3;          // rows 0..31 base, 16B chunks

    auto load_stage = [&](int s, int buf) {
        int k0 = s * 32;
        uint32_t sb = sbase + buf * STAGEB;
        const __half* gA = Ae + (size_t)r0 * KTOT + k0 + c0 * 8;
        const __half* gB = Be + (size_t)r0 * KTOT + k0 + c0 * 8;
        uint32_t so = r0 * PITCH + c0 * 16;
        #pragma unroll
        for (int i = 0; i < 4; i++) {
            size_t gstep = (size_t)(i * 32) * KTOT;
            uint32_t sstep = (i * 32) * PITCH;
            CP_ASYNC16(sb + so + sstep,        gA + gstep);
            CP_ASYNC16(sb + MATB + so + sstep, gB + gstep);
        }
        CP_COMMIT();
    };

    // ldmatrix lane decomposition
    int lr = lane & 7, lq = (lane >> 3) & 1, lh = lane >> 4;

    load_stage(0, 0);
    load_stage(1, 1);
    load_stage(2, 2);
    for (int s = 0; s < S; s++) {
        int buf = s & 3;
        if (s + 3 < S) {
            load_stage(s + 3, (s + 3) & 3);
            CP_WAITG(3);
        } else {
            int rem = S - 1 - s;
            if (rem == 2)      CP_WAITG(2);
            else if (rem == 1) CP_WAITG(1);
            else               CP_WAITG(0);
        }
        __syncthreads();

        uint32_t sb = sbase + buf * STAGEB;
        #pragma unroll
        for (int kk = 0; kk < 2; kk++) {
            uint32_t ah[4][4], bh[8][2];
            #pragma unroll
            for (int mi2 = 0; mi2 < 2; mi2++) {
                int row = wm*64 + mi2*32 + lr + lq*8;
                uint32_t off = row * PITCH + kk*32 + lh*16;
                ldsm4(ah[2*mi2], sb + off);
                int row2 = row + 16;
                uint32_t off2 = row2 * PITCH + kk*32 + lh*16;
                ldsm4(ah[2*mi2+1], sb + off2);
            }
            #pragma unroll
            for (int nj2 = 0; nj2 < 4; nj2++) {
                int row = wn*64 + nj2*16 + lr + lh*8;
                uint32_t off = row * PITCH + kk*32 + lq*16;
                uint32_t t[4];
                ldsm4(t, sb + MATB + off);
                bh[2*nj2][0] = t[0]; bh[2*nj2][1] = t[1];
                bh[2*nj2+1][0] = t[2]; bh[2*nj2+1][1] = t[3];
            }
            #pragma unroll
            for (int mi = 0; mi < 4; mi++)
                #pragma unroll
                for (int nj = 0; nj < 8; nj++)
                    mma16816(acc[mi][nj], ah[mi], bh[nj]);
        }
        __syncthreads();
    }

    // ---------------- epilogue --------------------------------------------
    int qr = lane >> 2, qc = lane & 3;
    float2 bv[8];
    #pragma unroll
    for (int nj = 0; nj < 8; nj++) {
        int colg = bn*128 + wn*64 + nj*8 + 2*qc;
        bv[nj] = *(const float2*)(bias + (size_t)e * NTOT + colg);
    }
    if (!PHASE2) {
        #pragma unroll
        for (int mi = 0; mi < 4; mi++)
            #pragma unroll
            for (int h = 0; h < 2; h++) {
                int rowg = bm*128 + wm*64 + mi*16 + qr + h*8;
                #pragma unroll
                for (int nj = 0; nj < 8; nj++) {
                    int colg = bn*128 + wn*64 + nj*8 + 2*qc;
                    float v0 = acc[mi][nj][2*h]   + bv[nj].x;
                    float v1 = acc[mi][nj][2*h+1] + bv[nj].y;
                    __half2 hv = __floats2half2_rn(gelu_exact(v0), gelu_exact(v1));
                    *(__half2*)(g_hh + (size_t)rowg * NTOT + colg) = hv;
                }
            }
    } else {
        #pragma unroll
        for (int mi = 0; mi < 4; mi++)
            #pragma unroll
            for (int h = 0; h < 2; h++) {
                int slot = bm*128 + wm*64 + mi*16 + qr + h*8;
                int tok = g_tok_of_slot[slot];
                if (tok >= 0) {
                    float sc = g_scale[tok];
                    float* orow = outp + (size_t)tok * NTOT;
                    #pragma unroll
                    for (int nj = 0; nj < 8; nj++) {
                        int colg = bn*128 + wn*64 + nj*8 + 2*qc;
                        float2 ov;
                        ov.x = (acc[mi][nj][2*h]   + bv[nj].x) * sc;
                        ov.y = (acc[mi][nj][2*h+1] + bv[nj].y) * sc;
                        *(float2*)(orow + colg) = ov;
                    }
                }
            }
    }
}

// ---------------- aux loss (deterministic reduction, 1 block) ---------------
__global__ void aux_kernel(float* __restrict__ out_aux)
{
    __shared__ float sh[1024];
    int t = threadIdx.x;
    float ls = 0.f;
    for (int n = t; n < NTOK; n += 1024) ls += g_lse2[n];
    float ps[NE] = {0,0,0,0,0,0,0,0};
    for (int n = t; n < NTOK; n += 1024) {
        #pragma unroll
        for (int e = 0; e < NE; e++) ps[e] += g_probs[n*NE + e];
    }
    __shared__ float red[NE + 1];
    sh[t] = ls; __syncthreads();
    for (int o = 512; o > 0; o >>= 1) { if (t < o) sh[t] += sh[t + o]; __syncthreads(); }
    if (t == 0) red[NE] = sh[0];
    __syncthreads();
    for (int e = 0; e < NE; e++) {
        sh[t] = ps[e]; __syncthreads();
        for (int o = 512; o > 0; o >>= 1) { if (t < o) sh[t] += sh[t + o]; __syncthreads(); }
        if (t == 0) red[e] = sh[0];
        __syncthreads();
    }
    if (t == 0) {
        float invN = 1.0f / (float)NTOK;
        float fb = 0.f;
        for (int e = 0; e < NE; e++) {
            float f_i = (float)g_counts[e] * invN;
            float p_i = red[e] * invN;
            fb += f_i * p_i;
        }
        float z = red[NE] * invN;
        out_aux[0] = 0.01f * (float)NE * fb + 0.001f * z;
    }
}

// ---------------------------------------------------------------------------
extern "C" void kernel_launch(void* const* d_in, const int* in_sizes, int n_in,
                              void* d_out, int out_size)
{
    const float* x  = (const float*)d_in[0];
    const float* Wg = (const float*)d_in[1];
    const float* W1 = (const float*)d_in[2];
    const float* b1 = (const float*)d_in[3];
    const float* W2 = (const float*)d_in[4];
    const float* b2 = (const float*)d_in[5];
    float* out = (float*)d_out;

    cudaFuncSetAttribute(tgemm_kernel<ND, NH, false>,
                         cudaFuncAttributeMaxDynamicSharedMemorySize, GSMEM);
    cudaFuncSetAttribute(tgemm_kernel<NH, ND, true>,
                         cudaFuncAttributeMaxDynamicSharedMemorySize, GSMEM);

    __half *xh, *hh, *w1h, *w2h;
    cudaGetSymbolAddress((void**)&xh,  g_xh);
    cudaGetSymbolAddress((void**)&hh,  g_hh);
    cudaGetSymbolAddress((void**)&w1h, g_w1h);
    cudaGetSymbolAddress((void**)&w2h, g_w2h);

    // weight transpose + fp16 convert (independent of routing)
    wconv_kernel<ND, NH><<<dim3(NH/32, ND/64, NE), dim3(32, 8)>>>(W1, w1h);
    wconv_kernel<NH, ND><<<dim3(ND/32, NH/64, NE), dim3(32, 8)>>>(W2, w2h);

    // routing chain
    router_kernel<<<NTOK/8, 256>>>(x, Wg);
    rank_kernel<<<1, 1024>>>();
    gather_kernel<<<NTOK, 256>>>(x, out);

    // GEMM1: [MT,ND] @ W1t -> gelu -> hidden (fp16)
    tgemm_kernel<ND, NH, false><<<dim3(NH/128, MT/128), 128, GSMEM>>>(
        xh, w1h, b1, out);
    // GEMM2: [MT,NH] @ W2t -> bias + scale -> scatter to out
    tgemm_kernel<NH, ND, true><<<dim3(ND/128, MT/128), 128, GSMEM>>>(
        hh, w2h, b2, out);

    if (out_size > NTOK * ND) {
        aux_kernel<<<1, 1024>>>(out + (size_t)NTOK * ND);
    }
}